// round 15
// baseline (speedup 1.0000x reference)
#include <cuda_runtime.h>
#include <cuda_fp16.h>
#include <cstdint>

#define TOKS 16384
#define HDIM 1024
#define IDIM 2048
#define NE   8
#define STG  4
#define STAGE_BYTES 24576           // A: 4 chunks x 256 rows x 16B = 16KB, B: 4 x 128 x 16B = 8KB
#define SMEM_BYTES  (STG * STAGE_BYTES)
#define RTR_BLOCKS (TOKS / 8)       // 2048 router blocks, placed FIRST in the prep grid
#define CVT_BLOCKS 27648

// ---------------- static scratch ----------------
__device__ int   g_cnt[16];
__device__ int   g_off[16];
__device__ int   g_tok[NE * TOKS];
__device__ float g_wt [NE * TOKS];
__device__ __align__(256) __half g_xh[(size_t)TOKS * HDIM];
__device__ __align__(256) __half g_Wgh[(size_t)(NE + 1) * IDIM * HDIM];  // slot NE = shared
__device__ __align__(256) __half g_Wuh[(size_t)(NE + 1) * IDIM * HDIM];
__device__ __align__(256) __half g_Wdh[(size_t)(NE + 1) * HDIM * IDIM];
__device__ __align__(256) __half g_hh[(size_t)3 * TOKS * IDIM];  // routed packed, shared at 2*TOKS

// ---------------- helpers ----------------
__device__ __forceinline__ uint32_t smem_u32(const void* p) {
    uint32_t a;
    asm("{ .reg .u64 t; cvta.to.shared.u64 t, %1; cvt.u32.u64 %0, t; }" : "=r"(a) : "l"(p));
    return a;
}
__device__ __forceinline__ void cp16(uint32_t dst, const __half* src, int sz) {
    asm volatile("cp.async.cg.shared.global [%0], [%1], 16, %2;"
                 :: "r"(dst), "l"(src), "r"(sz) : "memory");
}
__device__ __forceinline__ void cp_commit() { asm volatile("cp.async.commit_group;" ::: "memory"); }
__device__ __forceinline__ void cp_wait1()  { asm volatile("cp.async.wait_group 1;" ::: "memory"); }

__device__ __forceinline__ void ldsm4(uint32_t* r, uint32_t addr) {
    asm volatile("ldmatrix.sync.aligned.m8n8.x4.shared.b16 {%0,%1,%2,%3}, [%4];"
                 : "=r"(r[0]), "=r"(r[1]), "=r"(r[2]), "=r"(r[3]) : "r"(addr));
}
__device__ __forceinline__ void mma_f16(float* c, const uint32_t* a, uint32_t b0, uint32_t b1) {
    asm volatile(
        "mma.sync.aligned.m16n8k16.row.col.f32.f16.f16.f32 "
        "{%0,%1,%2,%3}, {%4,%5,%6,%7}, {%8,%9}, {%0,%1,%2,%3};\n"
        : "+f"(c[0]), "+f"(c[1]), "+f"(c[2]), "+f"(c[3])
        : "r"(a[0]), "r"(a[1]), "r"(a[2]), "r"(a[3]), "r"(b0), "r"(b1));
}

// ---------------- kernel: merged prep = router (blocks 0..2047, long jobs first) + weight cvt ----------------
// g_cnt is pre-zeroed by cudaMemsetAsync before this kernel.
__global__ void prep_kernel(const float* __restrict__ x,
                            const float* __restrict__ Wr,
                            const float* __restrict__ rb,
                            const float* __restrict__ Wg_s, const float* __restrict__ Wu_s,
                            const float* __restrict__ Wd_s, const float* __restrict__ Wg,
                            const float* __restrict__ Wu,   const float* __restrict__ Wd) {
    if (blockIdx.x >= RTR_BLOCKS) {
        // ---- weight convert: 2048 fp32 per block ----
        int b = blockIdx.x - RTR_BLOCKS;
        const float* src;
        __half* dst;
        if (b < 1024)       { src = Wg_s; dst = g_Wgh + (size_t)NE * IDIM * HDIM; }
        else if (b < 2048)  { src = Wu_s; dst = g_Wuh + (size_t)NE * IDIM * HDIM; b -= 1024; }
        else if (b < 3072)  { src = Wd_s; dst = g_Wdh + (size_t)NE * HDIM * IDIM; b -= 2048; }
        else if (b < 11264) { src = Wg;   dst = g_Wgh; b -= 3072; }
        else if (b < 19456) { src = Wu;   dst = g_Wuh; b -= 11264; }
        else                { src = Wd;   dst = g_Wdh; b -= 19456; }
        size_t i = ((size_t)b * 256 + threadIdx.x) * 8;
        float4 v0 = *(const float4*)(src + i);
        float4 v1 = *(const float4*)(src + i + 4);
        __half2 h[4];
        h[0] = __floats2half2_rn(v0.x, v0.y);
        h[1] = __floats2half2_rn(v0.z, v0.w);
        h[2] = __floats2half2_rn(v1.x, v1.y);
        h[3] = __floats2half2_rn(v1.z, v1.w);
        *(uint4*)(dst + i) = *(uint4*)h;
        return;
    }

    // ---- router (sigmoid top-2) + fused x -> fp16 convert ----
    __shared__ float sWr[NE][HDIM];
    int tid = threadIdx.x;
    for (int i = tid * 4; i < NE * HDIM; i += blockDim.x * 4)
        *(float4*)&sWr[0][i] = *(const float4*)&Wr[i];
    __syncthreads();

    int wid = tid >> 5, lane = tid & 31;
    int t = blockIdx.x * 8 + wid;
    const float* xr = x + (size_t)t * HDIM;
    __half* xh = g_xh + (size_t)t * HDIM;

    float acc[NE];
#pragma unroll
    for (int e = 0; e < NE; e++) acc[e] = 0.f;
#pragma unroll
    for (int i = 0; i < HDIM / 64; i++) {
        int k = 2 * lane + 64 * i;
        float2 v = *(const float2*)(xr + k);
        *(__half2*)(xh + k) = __floats2half2_rn(v.x, v.y);
#pragma unroll
        for (int e = 0; e < NE; e++) acc[e] += v.x * sWr[e][k] + v.y * sWr[e][k + 1];
    }
#pragma unroll
    for (int e = 0; e < NE; e++) {
#pragma unroll
        for (int off = 16; off > 0; off >>= 1)
            acc[e] += __shfl_xor_sync(0xffffffffu, acc[e], off);
    }
    if (lane == 0) {
        float best1 = -1e30f, best2 = -1e30f;
        int e1 = -1, e2 = -1;
#pragma unroll
        for (int e = 0; e < NE; e++) {
            float l = acc[e] + rb[e];
            if (l > best1) { best2 = best1; e2 = e1; best1 = l; e1 = e; }
            else if (l > best2) { best2 = l; e2 = e; }
        }
        float w1 = 1.f / (1.f + __expf(-best1));
        float w2 = 1.f / (1.f + __expf(-best2));
        int p1 = atomicAdd(&g_cnt[e1], 1);
        g_tok[e1 * TOKS + p1] = t;  g_wt[e1 * TOKS + p1] = w1;
        int p2 = atomicAdd(&g_cnt[e2], 1);
        g_tok[e2 * TOKS + p2] = t;  g_wt[e2 * TOKS + p2] = w2;
    }
}

// ---------------- kernel: prefix offsets ----------------
__global__ void offs_kernel() {
    if (threadIdx.x == 0) {
        int a = 0;
        for (int e = 0; e < NE; e++) { g_off[e] = a; a += g_cnt[e]; }
        g_off[NE] = 2 * TOKS;
    }
}

// fragment load macros (A stage 256 rows, B stage 128 rows at +16384; cb = k16-slice*2)
#define LOADA(buf, AB, cb) \
    _Pragma("unroll") \
    for (int mt = 0; mt < 2; mt++) { \
        int mrow = wm + mt * 16 + (lane & 7) + ((lane >> 3) & 1) * 8; \
        int mc = (cb) + ((lane >> 4) & 1); \
        ldsm4(afr[buf][mt], (AB) + (uint32_t)(mc * 256 + mrow) * 16); \
    }
#define LOADB(buf, BB, cb) \
    _Pragma("unroll") \
    for (int p = 0; p < 4; p++) { \
        int nrow = wn + p * 16 + (lane & 7) + ((lane >> 4) & 1) * 8; \
        int nc = (cb) + ((lane >> 3) & 1); \
        uint32_t t[4]; \
        ldsm4(t, (BB) + (uint32_t)(nc * 128 + nrow) * 16); \
        bfr[buf][2 * p][0] = t[0]; bfr[buf][2 * p][1] = t[1]; \
        bfr[buf][2 * p + 1][0] = t[2]; bfr[buf][2 * p + 1][1] = t[3]; \
    }
#define MMAALL(buf) \
    _Pragma("unroll") \
    for (int nt = 0; nt < 8; nt++) \
        _Pragma("unroll") \
        for (int mt = 0; mt < 2; mt++) \
            mma_f16(acc[mt][nt], afr[buf][mt], bfr[buf][nt][0], bfr[buf][nt][1]);

// smem per stage: A at (c*256+m)*16, B at 16384 + (c*128+n)*16
// ========== gate+up GEMM: BM=256 tokens, 64 out-cols (gate+up interleaved), 512 threads ==========
__global__ __launch_bounds__(512, 1) void gateup_kernel() {
    extern __shared__ char smem[];
    __shared__ int sTok[256];
    const uint32_t sb = smem_u32(smem);
    const int e = blockIdx.z;
    const int rows = (e == NE) ? TOKS : g_cnt[e];
    const int m0 = blockIdx.y * 256;
    if (m0 >= rows) return;
    const int n0 = blockIdx.x * 64;
    const __half* Bg = g_Wgh + (size_t)e * IDIM * HDIM;
    const __half* Bu = g_Wuh + (size_t)e * IDIM * HDIM;
    const int rowbase = g_off[e];
    const int tid = threadIdx.x, wid = tid >> 5, lane = tid & 31;
    const int wm = (wid & 7) * 32, wn = (wid >> 3) * 64;

    for (int m = tid; m < 256; m += 512) {
        int r = m0 + m;
        sTok[m] = (r < rows) ? ((e == NE) ? r : g_tok[e * TOKS + r]) : -1;
    }
    __syncthreads();

    // fill: A 1024 lines (2/thread), B 512 lines (1/thread)
    const __half* asrc[2]; int asz[2]; uint32_t aoff[2];
    const __half* bsrc; uint32_t boff;
#pragma unroll
    for (int i = 0; i < 2; i++) {
        int idx = tid + i * 512;
        int m = idx & 255, c = idx >> 8;
        int tok = sTok[m];
        asrc[i] = g_xh + (tok >= 0 ? (size_t)tok * HDIM : 0) + c * 8;
        asz[i]  = (tok >= 0) ? 16 : 0;
        aoff[i] = (uint32_t)(c * 256 + m) * 16;
    }
    {
        int n = tid & 127, c = tid >> 7;
        int mat = (n >> 5) & 1;
        int col = n0 + ((n >> 6) << 5) + (n & 31);
        bsrc = (mat ? Bu : Bg) + (size_t)col * HDIM + c * 8;
        boff = 16384u + (uint32_t)(c * 128 + n) * 16;
    }

    float acc[2][8][4];
#pragma unroll
    for (int mt = 0; mt < 2; mt++)
#pragma unroll
        for (int nt = 0; nt < 8; nt++)
#pragma unroll
            for (int i = 0; i < 4; i++) acc[mt][nt][i] = 0.f;

    const int KT = HDIM / 32;
    int fetch = 0;
#pragma unroll
    for (; fetch < STG - 1; fetch++) {
        uint32_t st = sb + fetch * STAGE_BYTES;
#pragma unroll
        for (int i = 0; i < 2; i++) cp16(st + aoff[i], asrc[i] + fetch * 32, asz[i]);
        cp16(st + boff, bsrc + fetch * 32, 16);
        cp_commit();
    }
    cp_wait1();                 // chunks 0,1 complete
    __syncthreads();

    uint32_t afr[2][2][4], bfr[2][8][2];
    LOADA(0, sb, 0)
    LOADB(0, sb + 16384u, 0)

    for (int c = 0; c < KT; c++) {
        const uint32_t Abc = sb + (c & (STG - 1)) * STAGE_BYTES;
        const uint32_t Bbc = Abc + 16384u;
        // slice 1 of chunk c into buf1, compute slice 0
        LOADA(1, Abc, 2)
        LOADB(1, Bbc, 2)
        MMAALL(0)
        // issue next fetch early (stage (c-1)%4: its readers all finished before prev barrier)
        if (fetch < KT) {
            uint32_t st = sb + (fetch & (STG - 1)) * STAGE_BYTES;
#pragma unroll
            for (int i = 0; i < 2; i++) cp16(st + aoff[i], asrc[i] + fetch * 32, asz[i]);
            cp16(st + boff, bsrc + fetch * 32, 16);
            fetch++;
        }
        cp_commit();
        // slice 0 of chunk c+1 into buf0 (complete per wait_group(1)), compute slice 1
        if (c + 1 < KT) {
            const uint32_t Abn = sb + ((c + 1) & (STG - 1)) * STAGE_BYTES;
            LOADA(0, Abn, 0)
            LOADB(0, Abn + 16384u, 0)
        }
        MMAALL(1)
        cp_wait1();
        __syncthreads();
    }

    // epilogue: h = silu(g)*u -> half
    const int cb = n0 + (wn >> 1);
#pragma unroll
    for (int mt = 0; mt < 2; mt++) {
#pragma unroll
        for (int h = 0; h < 2; h++) {
            int r = m0 + wm + mt * 16 + (lane >> 2) + h * 8;
            if (r < rows) {
                __half* hrow = g_hh + (size_t)(rowbase + r) * IDIM;
#pragma unroll
                for (int nt = 0; nt < 4; nt++) {
                    int col = cb + nt * 8 + 2 * (lane & 3);
                    float g0 = acc[mt][nt][h * 2 + 0], g1 = acc[mt][nt][h * 2 + 1];
                    float u0 = acc[mt][nt + 4][h * 2 + 0], u1 = acc[mt][nt + 4][h * 2 + 1];
                    float h0 = g0 * u0 / (1.f + __expf(-g0));
                    float h1 = g1 * u1 / (1.f + __expf(-g1));
                    *(__half2*)(hrow + col) = __floats2half2_rn(h0, h1);
                }
            }
        }
    }
}

// ========== down GEMM: BM=256, BN=128 over HDIM, K over IDIM, 512 threads ==========
__global__ __launch_bounds__(512, 1) void down_kernel(float* __restrict__ out, int shared_mode) {
    extern __shared__ char smem[];
    __shared__ int   sTok[256];
    __shared__ float sW[256];
    const uint32_t sb = smem_u32(smem);
    const int e = shared_mode ? NE : blockIdx.z;
    const int rows = shared_mode ? TOKS : g_cnt[e];
    const int m0 = blockIdx.y * 256;
    if (m0 >= rows) return;
    const int n0 = blockIdx.x * 128;
    const __half* Bw = g_Wdh + (size_t)e * HDIM * IDIM;
    const int rowbase = shared_mode ? 2 * TOKS : g_off[e];
    const int tid = threadIdx.x, wid = tid >> 5, lane = tid & 31;
    const int wm = (wid & 7) * 32, wn = (wid >> 3) * 64;

    for (int m = tid; m < 256; m += 512) {
        int r = m0 + m;
        if (r < rows) {
            sTok[m] = shared_mode ? r : g_tok[e * TOKS + r];
            sW[m]   = shared_mode ? 1.f : g_wt[e * TOKS + r];
        } else { sTok[m] = -1; sW[m] = 0.f; }
    }
    __syncthreads();

    const __half* asrc[2]; uint32_t aoff[2];
    const __half* bsrc; uint32_t boff;
#pragma unroll
    for (int i = 0; i < 2; i++) {
        int idx = tid + i * 512;
        int m = idx & 255, c = idx >> 8;
        asrc[i] = g_hh + (size_t)(rowbase + m0 + m) * IDIM + c * 8;
        aoff[i] = (uint32_t)(c * 256 + m) * 16;
    }
    {
        int n = tid & 127, c = tid >> 7;
        bsrc = Bw + (size_t)(n0 + n) * IDIM + c * 8;
        boff = 16384u + (uint32_t)(c * 128 + n) * 16;
    }

    float acc[2][8][4];
#pragma unroll
    for (int mt = 0; mt < 2; mt++)
#pragma unroll
        for (int nt = 0; nt < 8; nt++)
#pragma unroll
            for (int i = 0; i < 4; i++) acc[mt][nt][i] = 0.f;

    const int KT = IDIM / 32;
    int fetch = 0;
#pragma unroll
    for (; fetch < STG - 1; fetch++) {
        uint32_t st = sb + fetch * STAGE_BYTES;
#pragma unroll
        for (int i = 0; i < 2; i++) cp16(st + aoff[i], asrc[i] + fetch * 32, 16);
        cp16(st + boff, bsrc + fetch * 32, 16);
        cp_commit();
    }
    cp_wait1();
    __syncthreads();

    uint32_t afr[2][2][4], bfr[2][8][2];
    LOADA(0, sb, 0)
    LOADB(0, sb + 16384u, 0)

    for (int c = 0; c < KT; c++) {
        const uint32_t Abc = sb + (c & (STG - 1)) * STAGE_BYTES;
        const uint32_t Bbc = Abc + 16384u;
        LOADA(1, Abc, 2)
        LOADB(1, Bbc, 2)
        MMAALL(0)
        if (fetch < KT) {
            uint32_t st = sb + (fetch & (STG - 1)) * STAGE_BYTES;
#pragma unroll
            for (int i = 0; i < 2; i++) cp16(st + aoff[i], asrc[i] + fetch * 32, 16);
            cp16(st + boff, bsrc + fetch * 32, 16);
            fetch++;
        }
        cp_commit();
        if (c + 1 < KT) {
            const uint32_t Abn = sb + ((c + 1) & (STG - 1)) * STAGE_BYTES;
            LOADA(0, Abn, 0)
            LOADB(0, Abn + 16384u, 0)
        }
        MMAALL(1)
        cp_wait1();
        __syncthreads();
    }

    // epilogue: direct to out
#pragma unroll
    for (int mt = 0; mt < 2; mt++) {
#pragma unroll
        for (int h = 0; h < 2; h++) {
            int ml = wm + mt * 16 + (lane >> 2) + h * 8;
            int r = m0 + ml;
            if (r < rows) {
                int tok = sTok[ml];
                float w = sW[ml];
                float* drow = out + (size_t)tok * HDIM;
#pragma unroll
                for (int nt = 0; nt < 8; nt++) {
                    int col = n0 + wn + nt * 8 + 2 * (lane & 3);
                    float v0 = acc[mt][nt][h * 2 + 0];
                    float v1 = acc[mt][nt][h * 2 + 1];
                    if (shared_mode) {
                        *(float2*)(drow + col) = make_float2(v0, v1);
                    } else {
                        atomicAdd(drow + col + 0, w * v0);
                        atomicAdd(drow + col + 1, w * v1);
                    }
                }
            }
        }
    }
}

// ---------------- launch ----------------
extern "C" void kernel_launch(void* const* d_in, const int* in_sizes, int n_in,
                              void* d_out, int out_size) {
    (void)in_sizes; (void)n_in; (void)out_size;
    const float* x    = (const float*)d_in[0];
    const float* Wg_s = (const float*)d_in[1];
    const float* Wu_s = (const float*)d_in[2];
    const float* Wd_s = (const float*)d_in[3];
    const float* Wg   = (const float*)d_in[4];
    const float* Wu   = (const float*)d_in[5];
    const float* Wd   = (const float*)d_in[6];
    const float* Wr   = (const float*)d_in[7];
    const float* rb   = (const float*)d_in[8];
    float* out = (float*)d_out;

    cudaFuncSetAttribute(gateup_kernel, cudaFuncAttributeMaxDynamicSharedMemorySize, SMEM_BYTES);
    cudaFuncSetAttribute(down_kernel,   cudaFuncAttributeMaxDynamicSharedMemorySize, SMEM_BYTES);

    void* cnt_ptr = nullptr;
    cudaGetSymbolAddress(&cnt_ptr, g_cnt);
    cudaMemsetAsync(cnt_ptr, 0, 16 * sizeof(int));                  // zero router counters

    prep_kernel<<<RTR_BLOCKS + CVT_BLOCKS, 256>>>(x, Wr, rb, Wg_s, Wu_s, Wd_s, Wg, Wu, Wd);
    offs_kernel<<<1, 32>>>();
    gateup_kernel<<<dim3(IDIM / 64, TOKS / 256, NE + 1), 512, SMEM_BYTES>>>();
    down_kernel<<<dim3(HDIM / 128, TOKS / 256, 1), 512, SMEM_BYTES>>>(out, 1);
    down_kernel<<<dim3(HDIM / 128, TOKS / 256, NE), 512, SMEM_BYTES>>>(out, 0);
}

// round 16
// speedup vs baseline: 1.0022x; 1.0022x over previous
#include <cuda_runtime.h>
#include <cuda_fp16.h>
#include <cstdint>

#define TOKS 16384
#define HDIM 1024
#define IDIM 2048
#define NE   8
#define STG  4
#define STAGE_BYTES 24576           // A: 4 chunks x 256 rows x 16B = 16KB, B: 4 x 128 x 16B = 8KB
#define SMEM_BYTES  (STG * STAGE_BYTES)
#define CVT_BLOCKS 27648

// ---------------- static scratch ----------------
__device__ int   g_cnt[16];
__device__ int   g_off[16];
__device__ int   g_tok[NE * TOKS];
__device__ float g_wt [NE * TOKS];
__device__ __align__(256) __half g_xh[(size_t)TOKS * HDIM];
__device__ __align__(256) __half g_Wgh[(size_t)(NE + 1) * IDIM * HDIM];  // slot NE = shared
__device__ __align__(256) __half g_Wuh[(size_t)(NE + 1) * IDIM * HDIM];
__device__ __align__(256) __half g_Wdh[(size_t)(NE + 1) * HDIM * IDIM];
__device__ __align__(256) __half g_hh[(size_t)3 * TOKS * IDIM];  // routed packed, shared at 2*TOKS

// ---------------- helpers ----------------
__device__ __forceinline__ uint32_t smem_u32(const void* p) {
    uint32_t a;
    asm("{ .reg .u64 t; cvta.to.shared.u64 t, %1; cvt.u32.u64 %0, t; }" : "=r"(a) : "l"(p));
    return a;
}
__device__ __forceinline__ void cp16(uint32_t dst, const __half* src, int sz) {
    asm volatile("cp.async.cg.shared.global [%0], [%1], 16, %2;"
                 :: "r"(dst), "l"(src), "r"(sz) : "memory");
}
__device__ __forceinline__ void cp_commit() { asm volatile("cp.async.commit_group;" ::: "memory"); }
__device__ __forceinline__ void cp_wait1()  { asm volatile("cp.async.wait_group 1;" ::: "memory"); }

__device__ __forceinline__ void ldsm4(uint32_t* r, uint32_t addr) {
    asm volatile("ldmatrix.sync.aligned.m8n8.x4.shared.b16 {%0,%1,%2,%3}, [%4];"
                 : "=r"(r[0]), "=r"(r[1]), "=r"(r[2]), "=r"(r[3]) : "r"(addr));
}
__device__ __forceinline__ void mma_f16(float* c, const uint32_t* a, uint32_t b0, uint32_t b1) {
    asm volatile(
        "mma.sync.aligned.m16n8k16.row.col.f32.f16.f16.f32 "
        "{%0,%1,%2,%3}, {%4,%5,%6,%7}, {%8,%9}, {%0,%1,%2,%3};\n"
        : "+f"(c[0]), "+f"(c[1]), "+f"(c[2]), "+f"(c[3])
        : "r"(a[0]), "r"(a[1]), "r"(a[2]), "r"(a[3]), "r"(b0), "r"(b1));
}
__device__ __forceinline__ void red_add_v2(float* addr, float a, float b) {
    asm volatile("red.global.add.v2.f32 [%0], {%1, %2};"
                 :: "l"(addr), "f"(a), "f"(b) : "memory");
}

// ---------------- kernel: merged prep = weight cvt (blocks 0..27647) + router (blocks 27648..) ----------------
// g_cnt is pre-zeroed by cudaMemsetAsync before this kernel.
__global__ void prep_kernel(const float* __restrict__ x,
                            const float* __restrict__ Wr,
                            const float* __restrict__ rb,
                            const float* __restrict__ Wg_s, const float* __restrict__ Wu_s,
                            const float* __restrict__ Wd_s, const float* __restrict__ Wg,
                            const float* __restrict__ Wu,   const float* __restrict__ Wd) {
    if (blockIdx.x < CVT_BLOCKS) {
        // ---- weight convert: 2048 fp32 per block ----
        int b = blockIdx.x;
        const float* src;
        __half* dst;
        if (b < 1024)       { src = Wg_s; dst = g_Wgh + (size_t)NE * IDIM * HDIM; }
        else if (b < 2048)  { src = Wu_s; dst = g_Wuh + (size_t)NE * IDIM * HDIM; b -= 1024; }
        else if (b < 3072)  { src = Wd_s; dst = g_Wdh + (size_t)NE * HDIM * IDIM; b -= 2048; }
        else if (b < 11264) { src = Wg;   dst = g_Wgh; b -= 3072; }
        else if (b < 19456) { src = Wu;   dst = g_Wuh; b -= 11264; }
        else                { src = Wd;   dst = g_Wdh; b -= 19456; }
        size_t i = ((size_t)b * 256 + threadIdx.x) * 8;
        float4 v0 = *(const float4*)(src + i);
        float4 v1 = *(const float4*)(src + i + 4);
        __half2 h[4];
        h[0] = __floats2half2_rn(v0.x, v0.y);
        h[1] = __floats2half2_rn(v0.z, v0.w);
        h[2] = __floats2half2_rn(v1.x, v1.y);
        h[3] = __floats2half2_rn(v1.z, v1.w);
        *(uint4*)(dst + i) = *(uint4*)h;
        return;
    }

    // ---- router (sigmoid top-2) + fused x -> fp16 convert ----
    __shared__ float sWr[NE][HDIM];
    int tid = threadIdx.x;
    for (int i = tid * 4; i < NE * HDIM; i += blockDim.x * 4)
        *(float4*)&sWr[0][i] = *(const float4*)&Wr[i];
    __syncthreads();

    int wid = tid >> 5, lane = tid & 31;
    int t = (blockIdx.x - CVT_BLOCKS) * 8 + wid;
    const float* xr = x + (size_t)t * HDIM;
    __half* xh = g_xh + (size_t)t * HDIM;

    float acc[NE];
#pragma unroll
    for (int e = 0; e < NE; e++) acc[e] = 0.f;
#pragma unroll
    for (int i = 0; i < HDIM / 64; i++) {
        int k = 2 * lane + 64 * i;
        float2 v = *(const float2*)(xr + k);
        *(__half2*)(xh + k) = __floats2half2_rn(v.x, v.y);
#pragma unroll
        for (int e = 0; e < NE; e++) acc[e] += v.x * sWr[e][k] + v.y * sWr[e][k + 1];
    }
#pragma unroll
    for (int e = 0; e < NE; e++) {
#pragma unroll
        for (int off = 16; off > 0; off >>= 1)
            acc[e] += __shfl_xor_sync(0xffffffffu, acc[e], off);
    }
    if (lane == 0) {
        float best1 = -1e30f, best2 = -1e30f;
        int e1 = -1, e2 = -1;
#pragma unroll
        for (int e = 0; e < NE; e++) {
            float l = acc[e] + rb[e];
            if (l > best1) { best2 = best1; e2 = e1; best1 = l; e1 = e; }
            else if (l > best2) { best2 = l; e2 = e; }
        }
        float w1 = 1.f / (1.f + __expf(-best1));
        float w2 = 1.f / (1.f + __expf(-best2));
        int p1 = atomicAdd(&g_cnt[e1], 1);
        g_tok[e1 * TOKS + p1] = t;  g_wt[e1 * TOKS + p1] = w1;
        int p2 = atomicAdd(&g_cnt[e2], 1);
        g_tok[e2 * TOKS + p2] = t;  g_wt[e2 * TOKS + p2] = w2;
    }
}

// ---------------- kernel: prefix offsets ----------------
__global__ void offs_kernel() {
    if (threadIdx.x == 0) {
        int a = 0;
        for (int e = 0; e < NE; e++) { g_off[e] = a; a += g_cnt[e]; }
        g_off[NE] = 2 * TOKS;
    }
}

// fragment load macros (A stage 256 rows, B stage 128 rows at +16384; cb = k16-slice*2)
#define LOADA(buf, AB, cb) \
    _Pragma("unroll") \
    for (int mt = 0; mt < 2; mt++) { \
        int mrow = wm + mt * 16 + (lane & 7) + ((lane >> 3) & 1) * 8; \
        int mc = (cb) + ((lane >> 4) & 1); \
        ldsm4(afr[buf][mt], (AB) + (uint32_t)(mc * 256 + mrow) * 16); \
    }
#define LOADB(buf, BB, cb) \
    _Pragma("unroll") \
    for (int p = 0; p < 4; p++) { \
        int nrow = wn + p * 16 + (lane & 7) + ((lane >> 4) & 1) * 8; \
        int nc = (cb) + ((lane >> 3) & 1); \
        uint32_t t[4]; \
        ldsm4(t, (BB) + (uint32_t)(nc * 128 + nrow) * 16); \
        bfr[buf][2 * p][0] = t[0]; bfr[buf][2 * p][1] = t[1]; \
        bfr[buf][2 * p + 1][0] = t[2]; bfr[buf][2 * p + 1][1] = t[3]; \
    }
#define MMAALL(buf) \
    _Pragma("unroll") \
    for (int nt = 0; nt < 8; nt++) \
        _Pragma("unroll") \
        for (int mt = 0; mt < 2; mt++) \
            mma_f16(acc[mt][nt], afr[buf][mt], bfr[buf][nt][0], bfr[buf][nt][1]);

// smem per stage: A at (c*256+m)*16, B at 16384 + (c*128+n)*16
// ========== gate+up GEMM: BM=256 tokens, 64 out-cols (gate+up interleaved), 512 threads ==========
__global__ __launch_bounds__(512, 1) void gateup_kernel() {
    extern __shared__ char smem[];
    __shared__ int sTok[256];
    const uint32_t sb = smem_u32(smem);
    const int e = blockIdx.z;
    const int rows = (e == NE) ? TOKS : g_cnt[e];
    const int m0 = blockIdx.y * 256;
    if (m0 >= rows) return;
    const int n0 = blockIdx.x * 64;
    const __half* Bg = g_Wgh + (size_t)e * IDIM * HDIM;
    const __half* Bu = g_Wuh + (size_t)e * IDIM * HDIM;
    const int rowbase = g_off[e];
    const int tid = threadIdx.x, wid = tid >> 5, lane = tid & 31;
    const int wm = (wid & 7) * 32, wn = (wid >> 3) * 64;

    for (int m = tid; m < 256; m += 512) {
        int r = m0 + m;
        sTok[m] = (r < rows) ? ((e == NE) ? r : g_tok[e * TOKS + r]) : -1;
    }
    __syncthreads();

    // fill: A 1024 lines (2/thread), B 512 lines (1/thread)
    const __half* asrc[2]; int asz[2]; uint32_t aoff[2];
    const __half* bsrc; uint32_t boff;
#pragma unroll
    for (int i = 0; i < 2; i++) {
        int idx = tid + i * 512;
        int m = idx & 255, c = idx >> 8;
        int tok = sTok[m];
        asrc[i] = g_xh + (tok >= 0 ? (size_t)tok * HDIM : 0) + c * 8;
        asz[i]  = (tok >= 0) ? 16 : 0;
        aoff[i] = (uint32_t)(c * 256 + m) * 16;
    }
    {
        int n = tid & 127, c = tid >> 7;
        int mat = (n >> 5) & 1;
        int col = n0 + ((n >> 6) << 5) + (n & 31);
        bsrc = (mat ? Bu : Bg) + (size_t)col * HDIM + c * 8;
        boff = 16384u + (uint32_t)(c * 128 + n) * 16;
    }

    float acc[2][8][4];
#pragma unroll
    for (int mt = 0; mt < 2; mt++)
#pragma unroll
        for (int nt = 0; nt < 8; nt++)
#pragma unroll
            for (int i = 0; i < 4; i++) acc[mt][nt][i] = 0.f;

    const int KT = HDIM / 32;
    int fetch = 0;
#pragma unroll
    for (; fetch < STG - 1; fetch++) {
        uint32_t st = sb + fetch * STAGE_BYTES;
#pragma unroll
        for (int i = 0; i < 2; i++) cp16(st + aoff[i], asrc[i] + fetch * 32, asz[i]);
        cp16(st + boff, bsrc + fetch * 32, 16);
        cp_commit();
    }
    cp_wait1();                 // chunks 0,1 complete
    __syncthreads();

    uint32_t afr[2][2][4], bfr[2][8][2];
    LOADA(0, sb, 0)
    LOADB(0, sb + 16384u, 0)

    for (int c = 0; c < KT; c++) {
        const uint32_t Abc = sb + (c & (STG - 1)) * STAGE_BYTES;
        const uint32_t Bbc = Abc + 16384u;
        // slice 1 of chunk c into buf1, compute slice 0
        LOADA(1, Abc, 2)
        LOADB(1, Bbc, 2)
        MMAALL(0)
        // slice 0 of chunk c+1 into buf0 (stage complete per wait_group(1)), compute slice 1
        if (c + 1 < KT) {
            const uint32_t Abn = sb + ((c + 1) & (STG - 1)) * STAGE_BYTES;
            LOADA(0, Abn, 0)
            LOADB(0, Abn + 16384u, 0)
        }
        MMAALL(1)
        if (fetch < KT) {
            uint32_t st = sb + (fetch & (STG - 1)) * STAGE_BYTES;
#pragma unroll
            for (int i = 0; i < 2; i++) cp16(st + aoff[i], asrc[i] + fetch * 32, asz[i]);
            cp16(st + boff, bsrc + fetch * 32, 16);
            fetch++;
        }
        cp_commit();
        cp_wait1();
        __syncthreads();
    }

    // epilogue: h = silu(g)*u -> half
    const int cb = n0 + (wn >> 1);
#pragma unroll
    for (int mt = 0; mt < 2; mt++) {
#pragma unroll
        for (int h = 0; h < 2; h++) {
            int r = m0 + wm + mt * 16 + (lane >> 2) + h * 8;
            if (r < rows) {
                __half* hrow = g_hh + (size_t)(rowbase + r) * IDIM;
#pragma unroll
                for (int nt = 0; nt < 4; nt++) {
                    int col = cb + nt * 8 + 2 * (lane & 3);
                    float g0 = acc[mt][nt][h * 2 + 0], g1 = acc[mt][nt][h * 2 + 1];
                    float u0 = acc[mt][nt + 4][h * 2 + 0], u1 = acc[mt][nt + 4][h * 2 + 1];
                    float h0 = g0 * u0 / (1.f + __expf(-g0));
                    float h1 = g1 * u1 / (1.f + __expf(-g1));
                    *(__half2*)(hrow + col) = __floats2half2_rn(h0, h1);
                }
            }
        }
    }
}

// ========== down GEMM: BM=256, BN=128 over HDIM, K over IDIM, 512 threads ==========
__global__ __launch_bounds__(512, 1) void down_kernel(float* __restrict__ out, int shared_mode) {
    extern __shared__ char smem[];
    __shared__ int   sTok[256];
    __shared__ float sW[256];
    const uint32_t sb = smem_u32(smem);
    const int e = shared_mode ? NE : blockIdx.z;
    const int rows = shared_mode ? TOKS : g_cnt[e];
    const int m0 = blockIdx.y * 256;
    if (m0 >= rows) return;
    const int n0 = blockIdx.x * 128;
    const __half* Bw = g_Wdh + (size_t)e * HDIM * IDIM;
    const int rowbase = shared_mode ? 2 * TOKS : g_off[e];
    const int tid = threadIdx.x, wid = tid >> 5, lane = tid & 31;
    const int wm = (wid & 7) * 32, wn = (wid >> 3) * 64;

    for (int m = tid; m < 256; m += 512) {
        int r = m0 + m;
        if (r < rows) {
            sTok[m] = shared_mode ? r : g_tok[e * TOKS + r];
            sW[m]   = shared_mode ? 1.f : g_wt[e * TOKS + r];
        } else { sTok[m] = -1; sW[m] = 0.f; }
    }
    __syncthreads();

    const __half* asrc[2]; uint32_t aoff[2];
    const __half* bsrc; uint32_t boff;
#pragma unroll
    for (int i = 0; i < 2; i++) {
        int idx = tid + i * 512;
        int m = idx & 255, c = idx >> 8;
        asrc[i] = g_hh + (size_t)(rowbase + m0 + m) * IDIM + c * 8;
        aoff[i] = (uint32_t)(c * 256 + m) * 16;
    }
    {
        int n = tid & 127, c = tid >> 7;
        bsrc = Bw + (size_t)(n0 + n) * IDIM + c * 8;
        boff = 16384u + (uint32_t)(c * 128 + n) * 16;
    }

    float acc[2][8][4];
#pragma unroll
    for (int mt = 0; mt < 2; mt++)
#pragma unroll
        for (int nt = 0; nt < 8; nt++)
#pragma unroll
            for (int i = 0; i < 4; i++) acc[mt][nt][i] = 0.f;

    const int KT = IDIM / 32;
    int fetch = 0;
#pragma unroll
    for (; fetch < STG - 1; fetch++) {
        uint32_t st = sb + fetch * STAGE_BYTES;
#pragma unroll
        for (int i = 0; i < 2; i++) cp16(st + aoff[i], asrc[i] + fetch * 32, 16);
        cp16(st + boff, bsrc + fetch * 32, 16);
        cp_commit();
    }
    cp_wait1();
    __syncthreads();

    uint32_t afr[2][2][4], bfr[2][8][2];
    LOADA(0, sb, 0)
    LOADB(0, sb + 16384u, 0)

    for (int c = 0; c < KT; c++) {
        const uint32_t Abc = sb + (c & (STG - 1)) * STAGE_BYTES;
        const uint32_t Bbc = Abc + 16384u;
        LOADA(1, Abc, 2)
        LOADB(1, Bbc, 2)
        MMAALL(0)
        if (c + 1 < KT) {
            const uint32_t Abn = sb + ((c + 1) & (STG - 1)) * STAGE_BYTES;
            LOADA(0, Abn, 0)
            LOADB(0, Abn + 16384u, 0)
        }
        MMAALL(1)
        if (fetch < KT) {
            uint32_t st = sb + (fetch & (STG - 1)) * STAGE_BYTES;
#pragma unroll
            for (int i = 0; i < 2; i++) cp16(st + aoff[i], asrc[i] + fetch * 32, 16);
            cp16(st + boff, bsrc + fetch * 32, 16);
            fetch++;
        }
        cp_commit();
        cp_wait1();
        __syncthreads();
    }

    // epilogue: direct to out (shared: plain float2 stores; routed: vector red.add.v2)
#pragma unroll
    for (int mt = 0; mt < 2; mt++) {
#pragma unroll
        for (int h = 0; h < 2; h++) {
            int ml = wm + mt * 16 + (lane >> 2) + h * 8;
            int r = m0 + ml;
            if (r < rows) {
                int tok = sTok[ml];
                float w = sW[ml];
                float* drow = out + (size_t)tok * HDIM;
#pragma unroll
                for (int nt = 0; nt < 8; nt++) {
                    int col = n0 + wn + nt * 8 + 2 * (lane & 3);
                    float v0 = acc[mt][nt][h * 2 + 0];
                    float v1 = acc[mt][nt][h * 2 + 1];
                    if (shared_mode) {
                        *(float2*)(drow + col) = make_float2(v0, v1);
                    } else {
                        red_add_v2(drow + col, w * v0, w * v1);
                    }
                }
            }
        }
    }
}

// ---------------- launch ----------------
extern "C" void kernel_launch(void* const* d_in, const int* in_sizes, int n_in,
                              void* d_out, int out_size) {
    (void)in_sizes; (void)n_in; (void)out_size;
    const float* x    = (const float*)d_in[0];
    const float* Wg_s = (const float*)d_in[1];
    const float* Wu_s = (const float*)d_in[2];
    const float* Wd_s = (const float*)d_in[3];
    const float* Wg   = (const float*)d_in[4];
    const float* Wu   = (const float*)d_in[5];
    const float* Wd   = (const float*)d_in[6];
    const float* Wr   = (const float*)d_in[7];
    const float* rb   = (const float*)d_in[8];
    float* out = (float*)d_out;

    cudaFuncSetAttribute(gateup_kernel, cudaFuncAttributeMaxDynamicSharedMemorySize, SMEM_BYTES);
    cudaFuncSetAttribute(down_kernel,   cudaFuncAttributeMaxDynamicSharedMemorySize, SMEM_BYTES);

    void* cnt_ptr = nullptr;
    cudaGetSymbolAddress(&cnt_ptr, g_cnt);
    cudaMemsetAsync(cnt_ptr, 0, 16 * sizeof(int));                  // zero router counters

    prep_kernel<<<CVT_BLOCKS + TOKS / 8, 256>>>(x, Wr, rb, Wg_s, Wu_s, Wd_s, Wg, Wu, Wd);
    offs_kernel<<<1, 32>>>();
    gateup_kernel<<<dim3(IDIM / 64, TOKS / 256, NE + 1), 512, SMEM_BYTES>>>();
    down_kernel<<<dim3(HDIM / 128, TOKS / 256, 1), 512, SMEM_BYTES>>>(out, 1);
    down_kernel<<<dim3(HDIM / 128, TOKS / 256, NE), 512, SMEM_BYTES>>>(out, 0);
}